// round 13
// baseline (speedup 1.0000x reference)
#include <cuda_runtime.h>
#include <cuda_bf16.h>
#include <cstdint>
#include <cstddef>

// ---------------- Problem constants ----------------
#define BB 4
#define SS 2048
#define DD 1024
#define HH 16
#define HD 64
#define LL 4
#define WIN 256
#define MT (BB*SS)          // 8192 rows
#define D4 (4*DD)           // 4096

// ---------------- Scratch (device globals; no allocation) ----------------
__device__ float g_x [MT*DD];
__device__ float g_q [MT*DD];
__device__ float g_k [MT*DD];
__device__ float g_v [MT*DD];

#define MEL ((size_t)DD*DD)                 // 1M elems
#define AW2 ((size_t)MT*(DD+D4))
#define W_ELEMS  (49*MEL)
__device__ __nv_bfloat16 g_ahi[AW2];
__device__ __nv_bfloat16 g_alo[AW2];
__device__ __nv_bfloat16 g_whi[W_ELEMS];
__device__ __nv_bfloat16 g_wlo[W_ELEMS];

// weight region offsets (elements)
#define OQKV ((size_t)0)
#define OO  (12*MEL)
#define O1  (16*MEL)
#define O2  (32*MEL)
#define ODl (48*MEL)

// ---------------- small helpers ----------------
__device__ __forceinline__ uint32_t smem_u32(const void* p){
    uint32_t a;
    asm("{ .reg .u64 t; cvta.to.shared.u64 t, %1; cvt.u32.u64 %0, t; }"
        : "=r"(a) : "l"(p));
    return a;
}
__device__ __forceinline__ void cpa16(uint32_t s, const void* g){
    asm volatile("cp.async.cg.shared.global [%0], [%1], 16;" :: "r"(s), "l"(g));
}
__device__ __forceinline__ void ldsm4(uint32_t* d, uint32_t a){
    asm volatile("ldmatrix.sync.aligned.m8n8.x4.shared.b16 {%0,%1,%2,%3}, [%4];"
        : "=r"(d[0]), "=r"(d[1]), "=r"(d[2]), "=r"(d[3]) : "r"(a));
}
__device__ __forceinline__ void mma16816(float* c, const uint32_t* a, const uint32_t* b){
    asm volatile("mma.sync.aligned.m16n8k16.row.col.f32.bf16.bf16.f32 "
        "{%0,%1,%2,%3}, {%4,%5,%6,%7}, {%8,%9}, {%0,%1,%2,%3};"
        : "+f"(c[0]), "+f"(c[1]), "+f"(c[2]), "+f"(c[3])
        : "r"(a[0]), "r"(a[1]), "r"(a[2]), "r"(a[3]), "r"(b[0]), "r"(b[1]));
}

// ---------------- HMMA split-bf16 GEMM ----------------
// CTA tile 256x128, BK=32, 16 warps = 8(m) x 2(n), warp tile 32x64.
// 4-stage cp.async pipeline, one __syncthreads per iteration, 1 CTA/SM.
#define BM 256
#define BN 128
#define BK 32
#define ATILE (BM*64)                 // 16384 B
#define BTILE (BN*64)                 // 8192 B
#define STAGE (2*ATILE + 2*BTILE)     // 49152
#define NSTG 4
#define SMEMB (NSTG*STAGE)            // 196608
#define NTHR 512

__device__ __forceinline__ uint32_t swz(int r, int c){
    return (uint32_t)(r * 64 + ((c ^ ((r >> 1) & 3)) << 4));
}

enum { EPI_NONE = 0, EPI_SILU_SPLIT = 1, EPI_RESID = 2, EPI_TANH = 3, EPI_QKV = 5 };

template<int EPI>
__global__ __launch_bounds__(NTHR, 1)
void hgemm_k(const __nv_bfloat16* __restrict__ Ahi, const __nv_bfloat16* __restrict__ Alo,
             const __nv_bfloat16* __restrict__ Bhi, const __nv_bfloat16* __restrict__ Blo,
             const float* __restrict__ R, float* __restrict__ C,
             float* __restrict__ C2, float* __restrict__ C3,
             __nv_bfloat16* __restrict__ Hh, __nv_bfloat16* __restrict__ Hl,
             const float* __restrict__ CO, const float* __restrict__ SI,
             int N, int K)
{
    extern __shared__ char sm[];
    const uint32_t sb = smem_u32(sm);
    const int tid  = threadIdx.x;
    const int warp = tid >> 5;
    const int lane = tid & 31;
    const int m0 = blockIdx.y * BM;
    const int n0 = blockIdx.x * BN;
    const int wm = warp >> 1;            // 0..7
    const int wn = warp & 1;             // 0..1

    auto issue = [&](int st, int kc) {
        uint32_t base = sb + st * STAGE;
        #pragma unroll
        for (int it = 0; it < 2; it++) {              // A: 1024 chunk-slots
            int i = tid + it * NTHR;
            int r = i >> 2, c = i & 3;
            uint32_t so = base + swz(r, c);
            size_t g = (size_t)(m0 + r) * K + kc + c * 8;
            cpa16(so,          Ahi + g);
            cpa16(so + ATILE,  Alo + g);
        }
        {                                             // B: 512 chunk-slots
            int r = tid >> 2, c = tid & 3;
            uint32_t so = base + 2 * ATILE + swz(r, c);
            size_t g = (size_t)(n0 + r) * K + kc + c * 8;
            cpa16(so,          Bhi + g);
            cpa16(so + BTILE,  Blo + g);
        }
        asm volatile("cp.async.commit_group;");
    };

    float acc[2][8][4];
    #pragma unroll
    for (int i = 0; i < 2; i++)
        #pragma unroll
        for (int j = 0; j < 8; j++)
            #pragma unroll
            for (int e = 0; e < 4; e++) acc[i][j][e] = 0.f;

    const int nk = K / BK;
    issue(0, 0);
    issue(1, BK);
    issue(2, 2 * BK);
    int stg = 0;
    for (int i = 0; i < nk; i++) {
        if (i + 1 < nk) { asm volatile("cp.async.wait_group 2;"); }
        else            { asm volatile("cp.async.wait_group 0;"); }
        __syncthreads();
        if (i + 3 < nk) {
            int ns = stg + 3; if (ns >= NSTG) ns -= NSTG;
            issue(ns, (i + 3) * BK);
        }

        uint32_t base = sb + stg * STAGE;
        #pragma unroll
        for (int kk = 0; kk < 2; kk++) {
            uint32_t ah[2][4], al[2][4];
            #pragma unroll
            for (int mi = 0; mi < 2; mi++) {
                int r = wm * 32 + mi * 16 + (lane & 15);
                int c = kk * 2 + (lane >> 4);
                uint32_t ad = base + swz(r, c);
                ldsm4(ah[mi], ad);
                ldsm4(al[mi], ad + ATILE);
            }
            #pragma unroll
            for (int nh = 0; nh < 2; nh++) {         // np-pairs: {0,1}, {2,3}
                uint32_t th[2][4], tl[2][4];
                #pragma unroll
                for (int p2 = 0; p2 < 2; p2++) {
                    int np = nh * 2 + p2;
                    int r = wn * 64 + np * 16 + (lane & 7) + ((lane >> 4) & 1) * 8;
                    int c = kk * 2 + ((lane >> 3) & 1);
                    uint32_t bd = base + 2 * ATILE + swz(r, c);
                    ldsm4(th[p2], bd);
                    ldsm4(tl[p2], bd + BTILE);
                }
                #pragma unroll
                for (int p2 = 0; p2 < 2; p2++) {
                    int np = nh * 2 + p2;
                    #pragma unroll
                    for (int mi = 0; mi < 2; mi++) {
                        mma16816(acc[mi][np*2],   ah[mi], th[p2]);
                        mma16816(acc[mi][np*2],   ah[mi], tl[p2]);
                        mma16816(acc[mi][np*2],   al[mi], th[p2]);
                        mma16816(acc[mi][np*2+1], ah[mi], th[p2] + 2);
                        mma16816(acc[mi][np*2+1], ah[mi], tl[p2] + 2);
                        mma16816(acc[mi][np*2+1], al[mi], th[p2] + 2);
                    }
                }
            }
        }
        if (++stg >= NSTG) stg = 0;
    }

    // ---- epilogue ----
    if (EPI == EPI_QKV) {
        int seg = n0 >> 10;
        int nb  = n0 & 1023;
        float* dst = (seg == 0) ? C : ((seg == 1) ? C2 : C3);
        if (seg < 2) {
            #pragma unroll
            for (int mi = 0; mi < 2; mi++) {
                int row = m0 + wm * 32 + mi * 16 + (lane >> 2);
                int s0 = row & (SS - 1);
                int s1 = s0 + 8;
                #pragma unroll
                for (int np = 0; np < 4; np++) {
                    int d = np * 8 + (lane & 3) * 2;
                    float2 cA0 = *(const float2*)(CO + s0 * HD + d);
                    float2 sA0 = *(const float2*)(SI + s0 * HD + d);
                    float2 cB0 = *(const float2*)(CO + s0 * HD + d + 32);
                    float2 sB0 = *(const float2*)(SI + s0 * HD + d + 32);
                    float2 cA1 = *(const float2*)(CO + s1 * HD + d);
                    float2 sA1 = *(const float2*)(SI + s1 * HD + d);
                    float2 cB1 = *(const float2*)(CO + s1 * HD + d + 32);
                    float2 sB1 = *(const float2*)(SI + s1 * HD + d + 32);
                    float* x1 = acc[mi][np];
                    float* x2 = acc[mi][np + 4];
                    float o1[4], o2[4];
                    o1[0] = x1[0] * cA0.x - x2[0] * sA0.x;
                    o1[1] = x1[1] * cA0.y - x2[1] * sA0.y;
                    o1[2] = x1[2] * cA1.x - x2[2] * sA1.x;
                    o1[3] = x1[3] * cA1.y - x2[3] * sA1.y;
                    o2[0] = x2[0] * cB0.x + x1[0] * sB0.x;
                    o2[1] = x2[1] * cB0.y + x1[1] * sB0.y;
                    o2[2] = x2[2] * cB1.x + x1[2] * sB1.x;
                    o2[3] = x2[3] * cB1.y + x1[3] * sB1.y;
                    int col = nb + wn * 64 + d;
                    size_t g0 = (size_t)row * DD + col;
                    size_t g1 = (size_t)(row + 8) * DD + col;
                    *(float2*)(dst + g0)      = make_float2(o1[0], o1[1]);
                    *(float2*)(dst + g1)      = make_float2(o1[2], o1[3]);
                    *(float2*)(dst + g0 + 32) = make_float2(o2[0], o2[1]);
                    *(float2*)(dst + g1 + 32) = make_float2(o2[2], o2[3]);
                }
            }
        } else {
            #pragma unroll
            for (int mi = 0; mi < 2; mi++) {
                #pragma unroll
                for (int ni = 0; ni < 8; ni++) {
                    int row = m0 + wm * 32 + mi * 16 + (lane >> 2);
                    int col = nb + wn * 64 + ni * 8 + (lane & 3) * 2;
                    size_t g0 = (size_t)row * DD + col;
                    size_t g1 = (size_t)(row + 8) * DD + col;
                    *(float2*)(dst + g0) = make_float2(acc[mi][ni][0], acc[mi][ni][1]);
                    *(float2*)(dst + g1) = make_float2(acc[mi][ni][2], acc[mi][ni][3]);
                }
            }
        }
    } else {
        #pragma unroll
        for (int mi = 0; mi < 2; mi++) {
            #pragma unroll
            for (int ni = 0; ni < 8; ni++) {
                int row = m0 + wm * 32 + mi * 16 + (lane >> 2);
                int col = n0 + wn * 64 + ni * 8 + (lane & 3) * 2;
                float v[4] = { acc[mi][ni][0], acc[mi][ni][1], acc[mi][ni][2], acc[mi][ni][3] };
                size_t o0 = (size_t)row * N + col;
                size_t o1 = (size_t)(row + 8) * N + col;
                if (EPI == EPI_SILU_SPLIT) {
                    #pragma unroll
                    for (int e = 0; e < 4; e++) v[e] = v[e] / (1.0f + __expf(-v[e]));
                    __nv_bfloat16 h0 = __float2bfloat16(v[0]);
                    __nv_bfloat16 h1 = __float2bfloat16(v[1]);
                    __nv_bfloat16 h2 = __float2bfloat16(v[2]);
                    __nv_bfloat16 h3 = __float2bfloat16(v[3]);
                    *(__nv_bfloat162*)(Hh + o0) = __halves2bfloat162(h0, h1);
                    *(__nv_bfloat162*)(Hh + o1) = __halves2bfloat162(h2, h3);
                    *(__nv_bfloat162*)(Hl + o0) = __halves2bfloat162(
                        __float2bfloat16(v[0] - __bfloat162float(h0)),
                        __float2bfloat16(v[1] - __bfloat162float(h1)));
                    *(__nv_bfloat162*)(Hl + o1) = __halves2bfloat162(
                        __float2bfloat16(v[2] - __bfloat162float(h2)),
                        __float2bfloat16(v[3] - __bfloat162float(h3)));
                } else {
                    if (EPI == EPI_RESID) {
                        float2 r0 = *(const float2*)(R + o0);
                        float2 r1 = *(const float2*)(R + o1);
                        v[0] += r0.x; v[1] += r0.y; v[2] += r1.x; v[3] += r1.y;
                    } else if (EPI == EPI_TANH) {
                        #pragma unroll
                        for (int e = 0; e < 4; e++) v[e] = tanhf(v[e]);
                    }
                    *(float2*)(C + o0) = make_float2(v[0], v[1]);
                    *(float2*)(C + o1) = make_float2(v[2], v[3]);
                }
            }
        }
    }
}

// ---------------- fp32 -> bf16 hi/lo split (flat) ----------------
__global__ __launch_bounds__(256) void split_k(const float* __restrict__ x,
                                               __nv_bfloat16* __restrict__ hi,
                                               __nv_bfloat16* __restrict__ lo)
{
    size_t i = (size_t)blockIdx.x * 256 + threadIdx.x;
    float4 v = ((const float4*)x)[i];
    __nv_bfloat16 h0 = __float2bfloat16(v.x);
    __nv_bfloat16 h1 = __float2bfloat16(v.y);
    __nv_bfloat16 h2 = __float2bfloat16(v.z);
    __nv_bfloat16 h3 = __float2bfloat16(v.w);
    ((__nv_bfloat162*)hi)[i*2]   = __halves2bfloat162(h0, h1);
    ((__nv_bfloat162*)hi)[i*2+1] = __halves2bfloat162(h2, h3);
    ((__nv_bfloat162*)lo)[i*2]   = __halves2bfloat162(
        __float2bfloat16(v.x - __bfloat162float(h0)),
        __float2bfloat16(v.y - __bfloat162float(h1)));
    ((__nv_bfloat162*)lo)[i*2+1] = __halves2bfloat162(
        __float2bfloat16(v.z - __bfloat162float(h2)),
        __float2bfloat16(v.w - __bfloat162float(h3)));
}

// ---------------- fp32 W[K,N] -> transposed bf16 hi/lo WT[N,K] ----------------
__global__ __launch_bounds__(256) void splitT_k(const float* __restrict__ src,
                                                __nv_bfloat16* __restrict__ hi,
                                                __nv_bfloat16* __restrict__ lo,
                                                int K, int N, size_t dstStride)
{
    __shared__ float t[32][33];
    src += (size_t)blockIdx.z * (size_t)K * N;
    hi  += (size_t)blockIdx.z * dstStride;
    lo  += (size_t)blockIdx.z * dstStride;
    int n0 = blockIdx.x * 32, k0 = blockIdx.y * 32;
    int tx = threadIdx.x & 31, ty = threadIdx.x >> 5;
    #pragma unroll
    for (int i = ty; i < 32; i += 8)
        t[i][tx] = src[(size_t)(k0 + i) * N + n0 + tx];
    __syncthreads();
    #pragma unroll
    for (int i = ty; i < 32; i += 8) {
        float v = t[tx][i];
        __nv_bfloat16 h = __float2bfloat16(v);
        size_t o = (size_t)(n0 + i) * K + k0 + tx;
        hi[o] = h;
        lo[o] = __float2bfloat16(v - __bfloat162float(h));
    }
}

// ---------------- RMSNorm fused with bf16 split ----------------
__global__ __launch_bounds__(256) void rmsns_k(const float* __restrict__ X,
                                               __nv_bfloat16* __restrict__ Hh,
                                               __nv_bfloat16* __restrict__ Hl)
{
    __shared__ float red[8];
    const int row = blockIdx.x;
    const int tid = threadIdx.x;
    const float4* x4 = (const float4*)(X + (size_t)row * DD);
    float4 v = x4[tid];
    float s = v.x * v.x + v.y * v.y + v.z * v.z + v.w * v.w;
    #pragma unroll
    for (int o = 16; o; o >>= 1) s += __shfl_xor_sync(0xffffffffu, s, o);
    if ((tid & 31) == 0) red[tid >> 5] = s;
    __syncthreads();
    float tot = red[0] + red[1] + red[2] + red[3] + red[4] + red[5] + red[6] + red[7];
    float inv = rsqrtf(tot * (1.0f / DD) + 1e-6f);
    float o0 = v.x * inv, o1 = v.y * inv, o2 = v.z * inv, o3 = v.w * inv;
    __nv_bfloat16 h0 = __float2bfloat16(o0);
    __nv_bfloat16 h1 = __float2bfloat16(o1);
    __nv_bfloat16 h2 = __float2bfloat16(o2);
    __nv_bfloat16 h3 = __float2bfloat16(o3);
    size_t base = (size_t)row * (DD / 2) + tid * 2;
    ((__nv_bfloat162*)Hh)[base]     = __halves2bfloat162(h0, h1);
    ((__nv_bfloat162*)Hh)[base + 1] = __halves2bfloat162(h2, h3);
    ((__nv_bfloat162*)Hl)[base]     = __halves2bfloat162(
        __float2bfloat16(o0 - __bfloat162float(h0)),
        __float2bfloat16(o1 - __bfloat162float(h1)));
    ((__nv_bfloat162*)Hl)[base + 1] = __halves2bfloat162(
        __float2bfloat16(o2 - __bfloat162float(h2)),
        __float2bfloat16(o3 - __bfloat162float(h3)));
}

// ---------------- Sliding-window attention (flash-style, split-bf16 out) ----------------
#define ATT_SMEM 49408
#define ABR 32
#define ABC 64

__global__ __launch_bounds__(256) void attn_k(const float* __restrict__ Q,
                                              const float* __restrict__ K,
                                              const float* __restrict__ V,
                                              __nv_bfloat16* __restrict__ Oh,
                                              __nv_bfloat16* __restrict__ Ol)
{
    extern __shared__ float asm_[];
    float* Qs = asm_;                       // [32][64]
    float* Ks = asm_ + 2048;                // [64][65]
    float* Vs = asm_ + 2048 + 64 * 65;      // [64][64]
    float* Ps = Vs + 4096;                  // [8][4][64]

    const int tid  = threadIdx.x;
    const int warp = tid >> 5;
    const int lane = tid & 31;
    const int bh = blockIdx.x;
    const int b  = bh >> 4;
    const int h  = bh & 15;
    const int q0 = blockIdx.y * ABR;

    for (int i = tid; i < ABR * 64; i += 256) {
        int r = i >> 6, d = i & 63;
        Qs[r * 64 + d] = Q[((size_t)(b * SS + q0 + r) * HH + h) * HD + d];
    }

    float m[4], l[4], a0[4], a1[4];
    #pragma unroll
    for (int i = 0; i < 4; i++) { m[i] = -1e30f; l[i] = 0.f; a0[i] = 0.f; a1[i] = 0.f; }

    int c0 = (q0 > WIN - 1) ? ((q0 - (WIN - 1)) & ~(ABC - 1)) : 0;
    for (int c = c0; c <= q0; c += ABC) {
        __syncthreads();
        for (int i = tid; i < ABC * 64; i += 256) {
            int r = i >> 6, d = i & 63;
            size_t g = ((size_t)(b * SS + c + r) * HH + h) * HD + d;
            Ks[r * 65 + d] = K[g];
            Vs[r * 64 + d] = V[g];
        }
        __syncthreads();

        float s0[4] = {0.f, 0.f, 0.f, 0.f};
        float s1[4] = {0.f, 0.f, 0.f, 0.f};
        #pragma unroll
        for (int d = 0; d < 64; d++) {
            float k0 = Ks[lane * 65 + d];
            float k1 = Ks[(lane + 32) * 65 + d];
            #pragma unroll
            for (int ri = 0; ri < 4; ri++) {
                float qd = Qs[(warp * 4 + ri) * 64 + d];
                s0[ri] = fmaf(qd, k0, s0[ri]);
                s1[ri] = fmaf(qd, k1, s1[ri]);
            }
        }
        #pragma unroll
        for (int ri = 0; ri < 4; ri++) {
            int qpos = q0 + warp * 4 + ri;
            float t0 = s0[ri] * 0.125f;
            float t1 = s1[ri] * 0.125f;
            int df0 = qpos - (c + lane);
            int df1 = qpos - (c + lane + 32);
            if (!(df0 >= 0 && df0 < WIN)) t0 = -1e9f;
            if (!(df1 >= 0 && df1 < WIN)) t1 = -1e9f;

            float mx = fmaxf(t0, t1);
            #pragma unroll
            for (int o = 16; o; o >>= 1) mx = fmaxf(mx, __shfl_xor_sync(0xffffffffu, mx, o));
            float mnew = fmaxf(m[ri], mx);
            float scale = expf(m[ri] - mnew);
            m[ri] = mnew;

            float p0 = __expf(t0 - mnew);
            float p1 = __expf(t1 - mnew);
            float ls = p0 + p1;
            #pragma unroll
            for (int o = 16; o; o >>= 1) ls += __shfl_xor_sync(0xffffffffu, ls, o);
            l[ri] = l[ri] * scale + ls;
            a0[ri] *= scale; a1[ri] *= scale;

            Ps[(warp * 4 + ri) * 64 + lane]      = p0;
            Ps[(warp * 4 + ri) * 64 + lane + 32] = p1;
        }
        __syncwarp();
        #pragma unroll
        for (int j = 0; j < 64; j++) {
            float v0 = Vs[j * 64 + lane];
            float v1 = Vs[j * 64 + lane + 32];
            #pragma unroll
            for (int ri = 0; ri < 4; ri++) {
                float pj = Ps[(warp * 4 + ri) * 64 + j];
                a0[ri] = fmaf(pj, v0, a0[ri]);
                a1[ri] = fmaf(pj, v1, a1[ri]);
            }
        }
        __syncwarp();
    }

    #pragma unroll
    for (int ri = 0; ri < 4; ri++) {
        int r = warp * 4 + ri;
        size_t g = ((size_t)(b * SS + q0 + r) * HH + h) * HD;
        float invl = 1.0f / l[ri];
        float v0 = a0[ri] * invl;
        float v1 = a1[ri] * invl;
        __nv_bfloat16 h0 = __float2bfloat16(v0);
        __nv_bfloat16 h1 = __float2bfloat16(v1);
        Oh[g + lane]      = h0;
        Oh[g + lane + 32] = h1;
        Ol[g + lane]      = __float2bfloat16(v0 - __bfloat162float(h0));
        Ol[g + lane + 32] = __float2bfloat16(v1 - __bfloat162float(h1));
    }
}

// ---------------- host orchestration ----------------
extern "C" void kernel_launch(void* const* d_in, const int* in_sizes, int n_in,
                              void* d_out, int out_size)
{
    const float* latents = (const float*)d_in[0];
    const float* cosT    = (const float*)d_in[1];
    const float* sinT    = (const float*)d_in[2];
    const float* wq      = (const float*)d_in[3];
    const float* wk      = (const float*)d_in[4];
    const float* wv      = (const float*)d_in[5];
    const float* wo      = (const float*)d_in[6];
    const float* w1      = (const float*)d_in[7];
    const float* w2      = (const float*)d_in[8];
    const float* wdelta  = (const float*)d_in[9];
    float* out = (float*)d_out;

    float *x, *q, *k, *v;
    __nv_bfloat16 *ahi, *alo, *whi, *wlo;
    cudaGetSymbolAddress((void**)&x,   g_x);
    cudaGetSymbolAddress((void**)&q,   g_q);
    cudaGetSymbolAddress((void**)&k,   g_k);
    cudaGetSymbolAddress((void**)&v,   g_v);
    cudaGetSymbolAddress((void**)&ahi, g_ahi);
    cudaGetSymbolAddress((void**)&alo, g_alo);
    cudaGetSymbolAddress((void**)&whi, g_whi);
    cudaGetSymbolAddress((void**)&wlo, g_wlo);

    __nv_bfloat16* ahi2 = ahi + (size_t)MT * DD;
    __nv_bfloat16* alo2 = alo + (size_t)MT * DD;

    cudaFuncSetAttribute(hgemm_k<EPI_QKV>,        cudaFuncAttributeMaxDynamicSharedMemorySize, SMEMB);
    cudaFuncSetAttribute(hgemm_k<EPI_SILU_SPLIT>, cudaFuncAttributeMaxDynamicSharedMemorySize, SMEMB);
    cudaFuncSetAttribute(hgemm_k<EPI_RESID>,      cudaFuncAttributeMaxDynamicSharedMemorySize, SMEMB);
    cudaFuncSetAttribute(hgemm_k<EPI_TANH>,       cudaFuncAttributeMaxDynamicSharedMemorySize, SMEMB);
    cudaFuncSetAttribute(attn_k,                  cudaFuncAttributeMaxDynamicSharedMemorySize, ATT_SMEM);

    const dim3 tb(256);
    const dim3 tg(NTHR);
    // ---- weight conversion: QKV packed per layer, others transposed+split ----
    splitT_k<<<dim3(DD/32, DD/32, LL), tb>>>(wq, whi + OQKV,         wlo + OQKV,         DD, DD, 3*MEL);
    splitT_k<<<dim3(DD/32, DD/32, LL), tb>>>(wk, whi + OQKV + MEL,   wlo + OQKV + MEL,   DD, DD, 3*MEL);
    splitT_k<<<dim3(DD/32, DD/32, LL), tb>>>(wv, whi + OQKV + 2*MEL, wlo + OQKV + 2*MEL, DD, DD, 3*MEL);
    splitT_k<<<dim3(DD/32, DD/32, LL), tb>>>(wo, whi + OO,  wlo + OO,  DD, DD, MEL);
    splitT_k<<<dim3(D4/32, DD/32, LL), tb>>>(w1, whi + O1,  wlo + O1,  DD, D4, 4*MEL);
    splitT_k<<<dim3(DD/32, D4/32, LL), tb>>>(w2, whi + O2,  wlo + O2,  D4, DD, 4*MEL);
    split_k<<<(int)(MEL/4/256), tb>>>(wdelta, whi + ODl, wlo + ODl);

    const dim3 gQKV(3 * DD / BN, MT / BM);  // (24, 32)
    const dim3 gN(DD / BN, MT / BM);        // (8, 32)
    const dim3 gW(D4 / BN, MT / BM);        // (32, 32)
    const dim3 gA(BB * HH, SS / ABR);

    for (int li = 0; li < LL; li++) {
        const __nv_bfloat16* bQh = whi + OQKV + (size_t)li * 3 * MEL;
        const __nv_bfloat16* bQl = wlo + OQKV + (size_t)li * 3 * MEL;
        const __nv_bfloat16* boh = whi + OO  + (size_t)li * MEL;
        const __nv_bfloat16* bol = wlo + OO  + (size_t)li * MEL;
        const __nv_bfloat16* b1h = whi + O1  + (size_t)li * 4 * MEL;
        const __nv_bfloat16* b1l = wlo + O1  + (size_t)li * 4 * MEL;
        const __nv_bfloat16* b2h = whi + O2  + (size_t)li * 4 * MEL;
        const __nv_bfloat16* b2l = wlo + O2  + (size_t)li * 4 * MEL;

        const float* xin = (li == 0) ? latents : x;

        rmsns_k<<<MT, tb>>>(xin, ahi, alo);
        hgemm_k<EPI_QKV><<<gQKV, tg, SMEMB>>>(ahi, alo, bQh, bQl, nullptr, q, k, v,
                                              nullptr, nullptr, cosT, sinT, DD, DD);
        attn_k<<<gA, tb, ATT_SMEM>>>(q, k, v, ahi, alo);
        hgemm_k<EPI_RESID><<<gN, tg, SMEMB>>>(ahi, alo, boh, bol, xin, x, nullptr, nullptr,
                                              nullptr, nullptr, nullptr, nullptr, DD, DD);
        rmsns_k<<<MT, tb>>>(x, ahi, alo);
        hgemm_k<EPI_SILU_SPLIT><<<gW, tg, SMEMB>>>(ahi, alo, b1h, b1l, nullptr, nullptr, nullptr, nullptr,
                                                   ahi2, alo2, nullptr, nullptr, D4, DD);
        hgemm_k<EPI_RESID><<<gN, tg, SMEMB>>>(ahi2, alo2, b2h, b2l, x, x, nullptr, nullptr,
                                              nullptr, nullptr, nullptr, nullptr, DD, D4);
    }

    rmsns_k<<<MT, tb>>>(x, ahi, alo);
    hgemm_k<EPI_TANH><<<gN, tg, SMEMB>>>(ahi, alo, whi + ODl, wlo + ODl, nullptr, out, nullptr, nullptr,
                                         nullptr, nullptr, nullptr, nullptr, DD, DD);
}

// round 14
// speedup vs baseline: 1.0835x; 1.0835x over previous
#include <cuda_runtime.h>
#include <cuda_bf16.h>
#include <cstdint>
#include <cstddef>

// ---------------- Problem constants ----------------
#define BB 4
#define SS 2048
#define DD 1024
#define HH 16
#define HD 64
#define LL 4
#define WIN 256
#define MT (BB*SS)          // 8192 rows
#define D4 (4*DD)           // 4096

// ---------------- Scratch (device globals; no allocation) ----------------
__device__ float g_x [MT*DD];
__device__ float g_q [MT*DD];
__device__ float g_k [MT*DD];
__device__ float g_v [MT*DD];

#define MEL ((size_t)DD*DD)                 // 1M elems
#define AW2 ((size_t)MT*(DD+D4))
#define W_ELEMS  (49*MEL)
__device__ __nv_bfloat16 g_ahi[AW2];
__device__ __nv_bfloat16 g_alo[AW2];
__device__ __nv_bfloat16 g_whi[W_ELEMS];
__device__ __nv_bfloat16 g_wlo[W_ELEMS];

// weight region offsets (elements)
#define OQKV ((size_t)0)
#define OO  (12*MEL)
#define O1  (16*MEL)
#define O2  (32*MEL)
#define ODl (48*MEL)

// ---------------- small helpers ----------------
__device__ __forceinline__ uint32_t smem_u32(const void* p){
    uint32_t a;
    asm("{ .reg .u64 t; cvta.to.shared.u64 t, %1; cvt.u32.u64 %0, t; }"
        : "=r"(a) : "l"(p));
    return a;
}
__device__ __forceinline__ void cpa16(uint32_t s, const void* g){
    asm volatile("cp.async.cg.shared.global [%0], [%1], 16;" :: "r"(s), "l"(g));
}
__device__ __forceinline__ void ldsm4(uint32_t* d, uint32_t a){
    asm volatile("ldmatrix.sync.aligned.m8n8.x4.shared.b16 {%0,%1,%2,%3}, [%4];"
        : "=r"(d[0]), "=r"(d[1]), "=r"(d[2]), "=r"(d[3]) : "r"(a));
}
__device__ __forceinline__ void mma16816(float* c, const uint32_t* a, const uint32_t* b){
    asm volatile("mma.sync.aligned.m16n8k16.row.col.f32.bf16.bf16.f32 "
        "{%0,%1,%2,%3}, {%4,%5,%6,%7}, {%8,%9}, {%0,%1,%2,%3};"
        : "+f"(c[0]), "+f"(c[1]), "+f"(c[2]), "+f"(c[3])
        : "r"(a[0]), "r"(a[1]), "r"(a[2]), "r"(a[3]), "r"(b[0]), "r"(b[1]));
}

// ---------------- HMMA split-bf16 GEMM (R11 config: 128x128, 2 CTA/SM) ----------------
#define BM 128
#define BN 128
#define BK 32
#define ATILE (BM*64)                 // 8192 B
#define BTILE (BN*64)                 // 8192 B
#define STAGE (2*ATILE + 2*BTILE)     // 32768
#define NSTG 3
#define SMEMB (NSTG*STAGE)            // 98304

__device__ __forceinline__ uint32_t swz(int r, int c){
    return (uint32_t)(r * 64 + ((c ^ ((r >> 1) & 3)) << 4));
}

enum { EPI_NONE = 0, EPI_SILU_SPLIT = 1, EPI_RESID = 2, EPI_TANH = 3, EPI_QKV = 5 };

template<int EPI>
__global__ __launch_bounds__(256, 2)
void hgemm_k(const __nv_bfloat16* __restrict__ Ahi, const __nv_bfloat16* __restrict__ Alo,
             const __nv_bfloat16* __restrict__ Bhi, const __nv_bfloat16* __restrict__ Blo,
             const float* __restrict__ R, float* __restrict__ C,
             float* __restrict__ C2, float* __restrict__ C3,
             __nv_bfloat16* __restrict__ Hh, __nv_bfloat16* __restrict__ Hl,
             const float* __restrict__ CO, const float* __restrict__ SI,
             int N, int K)
{
    extern __shared__ char sm[];
    const uint32_t sb = smem_u32(sm);
    const int tid  = threadIdx.x;
    const int warp = tid >> 5;
    const int lane = tid & 31;
    const int m0 = blockIdx.y * BM;
    const int n0 = blockIdx.x * BN;
    const int wm = warp >> 1;
    const int wn = warp & 1;

    auto issue = [&](int st, int kc) {
        uint32_t base = sb + st * STAGE;
        #pragma unroll
        for (int it = 0; it < 2; it++) {
            int i = tid + it * 256;
            int r = i >> 2, c = i & 3;
            uint32_t so = base + swz(r, c);
            size_t g = (size_t)(m0 + r) * K + kc + c * 8;
            cpa16(so,          Ahi + g);
            cpa16(so + ATILE,  Alo + g);
        }
        #pragma unroll
        for (int it = 0; it < 2; it++) {
            int i = tid + it * 256;
            int r = i >> 2, c = i & 3;
            uint32_t so = base + 2 * ATILE + swz(r, c);
            size_t g = (size_t)(n0 + r) * K + kc + c * 8;
            cpa16(so,          Bhi + g);
            cpa16(so + BTILE,  Blo + g);
        }
        asm volatile("cp.async.commit_group;");
    };

    float acc[2][8][4];
    #pragma unroll
    for (int i = 0; i < 2; i++)
        #pragma unroll
        for (int j = 0; j < 8; j++)
            #pragma unroll
            for (int e = 0; e < 4; e++) acc[i][j][e] = 0.f;

    const int nk = K / BK;
    issue(0, 0);
    issue(1, BK);
    int stg = 0;
    for (int i = 0; i < nk; i++) {
        if (i + 1 < nk) { asm volatile("cp.async.wait_group 1;"); }
        else            { asm volatile("cp.async.wait_group 0;"); }
        __syncthreads();
        if (i + 2 < nk) {
            int ns = stg + 2; if (ns >= NSTG) ns -= NSTG;
            issue(ns, (i + 2) * BK);
        }

        uint32_t base = sb + stg * STAGE;
        #pragma unroll
        for (int kk = 0; kk < 2; kk++) {
            uint32_t ah[2][4], al[2][4];
            #pragma unroll
            for (int mi = 0; mi < 2; mi++) {
                int r = wm * 32 + mi * 16 + (lane & 15);
                int c = kk * 2 + (lane >> 4);
                uint32_t ad = base + swz(r, c);
                ldsm4(ah[mi], ad);
                ldsm4(al[mi], ad + ATILE);
            }
            #pragma unroll
            for (int nh = 0; nh < 2; nh++) {         // np-pairs: {0,1}, {2,3}
                uint32_t th[2][4], tl[2][4];
                #pragma unroll
                for (int p2 = 0; p2 < 2; p2++) {
                    int np = nh * 2 + p2;
                    int r = wn * 64 + np * 16 + (lane & 7) + ((lane >> 4) & 1) * 8;
                    int c = kk * 2 + ((lane >> 3) & 1);
                    uint32_t bd = base + 2 * ATILE + swz(r, c);
                    ldsm4(th[p2], bd);
                    ldsm4(tl[p2], bd + BTILE);
                }
                #pragma unroll
                for (int p2 = 0; p2 < 2; p2++) {
                    int np = nh * 2 + p2;
                    #pragma unroll
                    for (int mi = 0; mi < 2; mi++) {
                        mma16816(acc[mi][np*2],   ah[mi], th[p2]);
                        mma16816(acc[mi][np*2],   ah[mi], tl[p2]);
                        mma16816(acc[mi][np*2],   al[mi], th[p2]);
                        mma16816(acc[mi][np*2+1], ah[mi], th[p2] + 2);
                        mma16816(acc[mi][np*2+1], ah[mi], tl[p2] + 2);
                        mma16816(acc[mi][np*2+1], al[mi], th[p2] + 2);
                    }
                }
            }
        }
        if (++stg >= NSTG) stg = 0;
    }

    // ---- epilogue ----
    if (EPI == EPI_QKV) {
        int seg = n0 >> 10;
        int nb  = n0 & 1023;
        float* dst = (seg == 0) ? C : ((seg == 1) ? C2 : C3);
        if (seg < 2) {
            #pragma unroll
            for (int mi = 0; mi < 2; mi++) {
                int row = m0 + wm * 32 + mi * 16 + (lane >> 2);
                int s0 = row & (SS - 1);
                int s1 = s0 + 8;
                #pragma unroll
                for (int np = 0; np < 4; np++) {
                    int d = np * 8 + (lane & 3) * 2;
                    float2 cA0 = *(const float2*)(CO + s0 * HD + d);
                    float2 sA0 = *(const float2*)(SI + s0 * HD + d);
                    float2 cB0 = *(const float2*)(CO + s0 * HD + d + 32);
                    float2 sB0 = *(const float2*)(SI + s0 * HD + d + 32);
                    float2 cA1 = *(const float2*)(CO + s1 * HD + d);
                    float2 sA1 = *(const float2*)(SI + s1 * HD + d);
                    float2 cB1 = *(const float2*)(CO + s1 * HD + d + 32);
                    float2 sB1 = *(const float2*)(SI + s1 * HD + d + 32);
                    float* x1 = acc[mi][np];
                    float* x2 = acc[mi][np + 4];
                    float o1[4], o2[4];
                    o1[0] = x1[0] * cA0.x - x2[0] * sA0.x;
                    o1[1] = x1[1] * cA0.y - x2[1] * sA0.y;
                    o1[2] = x1[2] * cA1.x - x2[2] * sA1.x;
                    o1[3] = x1[3] * cA1.y - x2[3] * sA1.y;
                    o2[0] = x2[0] * cB0.x + x1[0] * sB0.x;
                    o2[1] = x2[1] * cB0.y + x1[1] * sB0.y;
                    o2[2] = x2[2] * cB1.x + x1[2] * sB1.x;
                    o2[3] = x2[3] * cB1.y + x1[3] * sB1.y;
                    int col = nb + wn * 64 + d;
                    size_t g0 = (size_t)row * DD + col;
                    size_t g1 = (size_t)(row + 8) * DD + col;
                    *(float2*)(dst + g0)      = make_float2(o1[0], o1[1]);
                    *(float2*)(dst + g1)      = make_float2(o1[2], o1[3]);
                    *(float2*)(dst + g0 + 32) = make_float2(o2[0], o2[1]);
                    *(float2*)(dst + g1 + 32) = make_float2(o2[2], o2[3]);
                }
            }
        } else {
            #pragma unroll
            for (int mi = 0; mi < 2; mi++) {
                #pragma unroll
                for (int ni = 0; ni < 8; ni++) {
                    int row = m0 + wm * 32 + mi * 16 + (lane >> 2);
                    int col = nb + wn * 64 + ni * 8 + (lane & 3) * 2;
                    size_t g0 = (size_t)row * DD + col;
                    size_t g1 = (size_t)(row + 8) * DD + col;
                    *(float2*)(dst + g0) = make_float2(acc[mi][ni][0], acc[mi][ni][1]);
                    *(float2*)(dst + g1) = make_float2(acc[mi][ni][2], acc[mi][ni][3]);
                }
            }
        }
    } else {
        #pragma unroll
        for (int mi = 0; mi < 2; mi++) {
            #pragma unroll
            for (int ni = 0; ni < 8; ni++) {
                int row = m0 + wm * 32 + mi * 16 + (lane >> 2);
                int col = n0 + wn * 64 + ni * 8 + (lane & 3) * 2;
                float v[4] = { acc[mi][ni][0], acc[mi][ni][1], acc[mi][ni][2], acc[mi][ni][3] };
                size_t o0 = (size_t)row * N + col;
                size_t o1 = (size_t)(row + 8) * N + col;
                if (EPI == EPI_SILU_SPLIT) {
                    #pragma unroll
                    for (int e = 0; e < 4; e++) v[e] = v[e] / (1.0f + __expf(-v[e]));
                    __nv_bfloat16 h0 = __float2bfloat16(v[0]);
                    __nv_bfloat16 h1 = __float2bfloat16(v[1]);
                    __nv_bfloat16 h2 = __float2bfloat16(v[2]);
                    __nv_bfloat16 h3 = __float2bfloat16(v[3]);
                    *(__nv_bfloat162*)(Hh + o0) = __halves2bfloat162(h0, h1);
                    *(__nv_bfloat162*)(Hh + o1) = __halves2bfloat162(h2, h3);
                    *(__nv_bfloat162*)(Hl + o0) = __halves2bfloat162(
                        __float2bfloat16(v[0] - __bfloat162float(h0)),
                        __float2bfloat16(v[1] - __bfloat162float(h1)));
                    *(__nv_bfloat162*)(Hl + o1) = __halves2bfloat162(
                        __float2bfloat16(v[2] - __bfloat162float(h2)),
                        __float2bfloat16(v[3] - __bfloat162float(h3)));
                } else {
                    if (EPI == EPI_RESID) {
                        float2 r0 = *(const float2*)(R + o0);
                        float2 r1 = *(const float2*)(R + o1);
                        v[0] += r0.x; v[1] += r0.y; v[2] += r1.x; v[3] += r1.y;
                    } else if (EPI == EPI_TANH) {
                        #pragma unroll
                        for (int e = 0; e < 4; e++) v[e] = tanhf(v[e]);
                    }
                    *(float2*)(C + o0) = make_float2(v[0], v[1]);
                    *(float2*)(C + o1) = make_float2(v[2], v[3]);
                }
            }
        }
    }
}

// ---------------- fp32 -> bf16 hi/lo split (flat) ----------------
__global__ __launch_bounds__(256) void split_k(const float* __restrict__ x,
                                               __nv_bfloat16* __restrict__ hi,
                                               __nv_bfloat16* __restrict__ lo)
{
    size_t i = (size_t)blockIdx.x * 256 + threadIdx.x;
    float4 v = ((const float4*)x)[i];
    __nv_bfloat16 h0 = __float2bfloat16(v.x);
    __nv_bfloat16 h1 = __float2bfloat16(v.y);
    __nv_bfloat16 h2 = __float2bfloat16(v.z);
    __nv_bfloat16 h3 = __float2bfloat16(v.w);
    ((__nv_bfloat162*)hi)[i*2]   = __halves2bfloat162(h0, h1);
    ((__nv_bfloat162*)hi)[i*2+1] = __halves2bfloat162(h2, h3);
    ((__nv_bfloat162*)lo)[i*2]   = __halves2bfloat162(
        __float2bfloat16(v.x - __bfloat162float(h0)),
        __float2bfloat16(v.y - __bfloat162float(h1)));
    ((__nv_bfloat162*)lo)[i*2+1] = __halves2bfloat162(
        __float2bfloat16(v.z - __bfloat162float(h2)),
        __float2bfloat16(v.w - __bfloat162float(h3)));
}

// ---------------- fp32 W[K,N] -> transposed bf16 hi/lo WT[N,K] ----------------
__global__ __launch_bounds__(256) void splitT_k(const float* __restrict__ src,
                                                __nv_bfloat16* __restrict__ hi,
                                                __nv_bfloat16* __restrict__ lo,
                                                int K, int N, size_t dstStride)
{
    __shared__ float t[32][33];
    src += (size_t)blockIdx.z * (size_t)K * N;
    hi  += (size_t)blockIdx.z * dstStride;
    lo  += (size_t)blockIdx.z * dstStride;
    int n0 = blockIdx.x * 32, k0 = blockIdx.y * 32;
    int tx = threadIdx.x & 31, ty = threadIdx.x >> 5;
    #pragma unroll
    for (int i = ty; i < 32; i += 8)
        t[i][tx] = src[(size_t)(k0 + i) * N + n0 + tx];
    __syncthreads();
    #pragma unroll
    for (int i = ty; i < 32; i += 8) {
        float v = t[tx][i];
        __nv_bfloat16 h = __float2bfloat16(v);
        size_t o = (size_t)(n0 + i) * K + k0 + tx;
        hi[o] = h;
        lo[o] = __float2bfloat16(v - __bfloat162float(h));
    }
}

// ---------------- RMSNorm fused with bf16 split ----------------
__global__ __launch_bounds__(256) void rmsns_k(const float* __restrict__ X,
                                               __nv_bfloat16* __restrict__ Hh,
                                               __nv_bfloat16* __restrict__ Hl)
{
    __shared__ float red[8];
    const int row = blockIdx.x;
    const int tid = threadIdx.x;
    const float4* x4 = (const float4*)(X + (size_t)row * DD);
    float4 v = x4[tid];
    float s = v.x * v.x + v.y * v.y + v.z * v.z + v.w * v.w;
    #pragma unroll
    for (int o = 16; o; o >>= 1) s += __shfl_xor_sync(0xffffffffu, s, o);
    if ((tid & 31) == 0) red[tid >> 5] = s;
    __syncthreads();
    float tot = red[0] + red[1] + red[2] + red[3] + red[4] + red[5] + red[6] + red[7];
    float inv = rsqrtf(tot * (1.0f / DD) + 1e-6f);
    float o0 = v.x * inv, o1 = v.y * inv, o2 = v.z * inv, o3 = v.w * inv;
    __nv_bfloat16 h0 = __float2bfloat16(o0);
    __nv_bfloat16 h1 = __float2bfloat16(o1);
    __nv_bfloat16 h2 = __float2bfloat16(o2);
    __nv_bfloat16 h3 = __float2bfloat16(o3);
    size_t base = (size_t)row * (DD / 2) + tid * 2;
    ((__nv_bfloat162*)Hh)[base]     = __halves2bfloat162(h0, h1);
    ((__nv_bfloat162*)Hh)[base + 1] = __halves2bfloat162(h2, h3);
    ((__nv_bfloat162*)Hl)[base]     = __halves2bfloat162(
        __float2bfloat16(o0 - __bfloat162float(h0)),
        __float2bfloat16(o1 - __bfloat162float(h1)));
    ((__nv_bfloat162*)Hl)[base + 1] = __halves2bfloat162(
        __float2bfloat16(o2 - __bfloat162float(h2)),
        __float2bfloat16(o3 - __bfloat162float(h3)));
}

// ---------------- Sliding-window attention (flash-style, split-bf16 out) ----------------
// q-tile 64 rows, 512 threads (16 warps x 4 rows). Per-row math identical to the
// 32-row version -> bit-exact results; K/V smem fills amortized over 2x rows.
// Dynamic smem (floats): Qs[64][64], Ks[64][65], Vs[64][64], Ps[64][64]
#define ABR 64
#define ABC 64
#define ATT_THR 512
#define ATT_SMEM ((64*64 + 64*65 + 64*64 + 64*64) * 4)   // 65792 B

__global__ __launch_bounds__(ATT_THR) void attn_k(const float* __restrict__ Q,
                                                  const float* __restrict__ K,
                                                  const float* __restrict__ V,
                                                  __nv_bfloat16* __restrict__ Oh,
                                                  __nv_bfloat16* __restrict__ Ol)
{
    extern __shared__ float asm_[];
    float* Qs = asm_;                       // [64][64]
    float* Ks = asm_ + 4096;                // [64][65]
    float* Vs = Ks + 64 * 65;               // [64][64]
    float* Ps = Vs + 4096;                  // [64][64]

    const int tid  = threadIdx.x;
    const int warp = tid >> 5;              // 0..15
    const int lane = tid & 31;
    const int bh = blockIdx.x;
    const int b  = bh >> 4;
    const int h  = bh & 15;
    const int q0 = blockIdx.y * ABR;

    for (int i = tid; i < ABR * 64; i += ATT_THR) {
        int r = i >> 6, d = i & 63;
        Qs[r * 64 + d] = Q[((size_t)(b * SS + q0 + r) * HH + h) * HD + d];
    }

    float m[4], l[4], a0[4], a1[4];
    #pragma unroll
    for (int i = 0; i < 4; i++) { m[i] = -1e30f; l[i] = 0.f; a0[i] = 0.f; a1[i] = 0.f; }

    int c0 = (q0 > WIN - 1) ? ((q0 - (WIN - 1)) & ~(ABC - 1)) : 0;
    for (int c = c0; c <= q0; c += ABC) {
        __syncthreads();
        for (int i = tid; i < ABC * 64; i += ATT_THR) {
            int r = i >> 6, d = i & 63;
            size_t g = ((size_t)(b * SS + c + r) * HH + h) * HD + d;
            Ks[r * 65 + d] = K[g];
            Vs[r * 64 + d] = V[g];
        }
        __syncthreads();

        float s0[4] = {0.f, 0.f, 0.f, 0.f};
        float s1[4] = {0.f, 0.f, 0.f, 0.f};
        #pragma unroll
        for (int d = 0; d < 64; d++) {
            float k0 = Ks[lane * 65 + d];
            float k1 = Ks[(lane + 32) * 65 + d];
            #pragma unroll
            for (int ri = 0; ri < 4; ri++) {
                float qd = Qs[(warp * 4 + ri) * 64 + d];
                s0[ri] = fmaf(qd, k0, s0[ri]);
                s1[ri] = fmaf(qd, k1, s1[ri]);
            }
        }
        #pragma unroll
        for (int ri = 0; ri < 4; ri++) {
            int qpos = q0 + warp * 4 + ri;
            float t0 = s0[ri] * 0.125f;
            float t1 = s1[ri] * 0.125f;
            int df0 = qpos - (c + lane);
            int df1 = qpos - (c + lane + 32);
            if (!(df0 >= 0 && df0 < WIN)) t0 = -1e9f;
            if (!(df1 >= 0 && df1 < WIN)) t1 = -1e9f;

            float mx = fmaxf(t0, t1);
            #pragma unroll
            for (int o = 16; o; o >>= 1) mx = fmaxf(mx, __shfl_xor_sync(0xffffffffu, mx, o));
            float mnew = fmaxf(m[ri], mx);
            float scale = expf(m[ri] - mnew);
            m[ri] = mnew;

            float p0 = __expf(t0 - mnew);
            float p1 = __expf(t1 - mnew);
            float ls = p0 + p1;
            #pragma unroll
            for (int o = 16; o; o >>= 1) ls += __shfl_xor_sync(0xffffffffu, ls, o);
            l[ri] = l[ri] * scale + ls;
            a0[ri] *= scale; a1[ri] *= scale;

            Ps[(warp * 4 + ri) * 64 + lane]      = p0;
            Ps[(warp * 4 + ri) * 64 + lane + 32] = p1;
        }
        __syncwarp();
        #pragma unroll
        for (int j = 0; j < 64; j++) {
            float v0 = Vs[j * 64 + lane];
            float v1 = Vs[j * 64 + lane + 32];
            #pragma unroll
            for (int ri = 0; ri < 4; ri++) {
                float pj = Ps[(warp * 4 + ri) * 64 + j];
                a0[ri] = fmaf(pj, v0, a0[ri]);
                a1[ri] = fmaf(pj, v1, a1[ri]);
            }
        }
        __syncwarp();
    }

    #pragma unroll
    for (int ri = 0; ri < 4; ri++) {
        int r = warp * 4 + ri;
        size_t g = ((size_t)(b * SS + q0 + r) * HH + h) * HD;
        float invl = 1.0f / l[ri];
        float v0 = a0[ri] * invl;
        float v1 = a1[ri] * invl;
        __nv_bfloat16 h0 = __float2bfloat16(v0);
        __nv_bfloat16 h1 = __float2bfloat16(v1);
        Oh[g + lane]      = h0;
        Oh[g + lane + 32] = h1;
        Ol[g + lane]      = __float2bfloat16(v0 - __bfloat162float(h0));
        Ol[g + lane + 32] = __float2bfloat16(v1 - __bfloat162float(h1));
    }
}

// ---------------- host orchestration ----------------
extern "C" void kernel_launch(void* const* d_in, const int* in_sizes, int n_in,
                              void* d_out, int out_size)
{
    const float* latents = (const float*)d_in[0];
    const float* cosT    = (const float*)d_in[1];
    const float* sinT    = (const float*)d_in[2];
    const float* wq      = (const float*)d_in[3];
    const float* wk      = (const float*)d_in[4];
    const float* wv      = (const float*)d_in[5];
    const float* wo      = (const float*)d_in[6];
    const float* w1      = (const float*)d_in[7];
    const float* w2      = (const float*)d_in[8];
    const float* wdelta  = (const float*)d_in[9];
    float* out = (float*)d_out;

    float *x, *q, *k, *v;
    __nv_bfloat16 *ahi, *alo, *whi, *wlo;
    cudaGetSymbolAddress((void**)&x,   g_x);
    cudaGetSymbolAddress((void**)&q,   g_q);
    cudaGetSymbolAddress((void**)&k,   g_k);
    cudaGetSymbolAddress((void**)&v,   g_v);
    cudaGetSymbolAddress((void**)&ahi, g_ahi);
    cudaGetSymbolAddress((void**)&alo, g_alo);
    cudaGetSymbolAddress((void**)&whi, g_whi);
    cudaGetSymbolAddress((void**)&wlo, g_wlo);

    __nv_bfloat16* ahi2 = ahi + (size_t)MT * DD;
    __nv_bfloat16* alo2 = alo + (size_t)MT * DD;

    cudaFuncSetAttribute(hgemm_k<EPI_QKV>,        cudaFuncAttributeMaxDynamicSharedMemorySize, SMEMB);
    cudaFuncSetAttribute(hgemm_k<EPI_SILU_SPLIT>, cudaFuncAttributeMaxDynamicSharedMemorySize, SMEMB);
    cudaFuncSetAttribute(hgemm_k<EPI_RESID>,      cudaFuncAttributeMaxDynamicSharedMemorySize, SMEMB);
    cudaFuncSetAttribute(hgemm_k<EPI_TANH>,       cudaFuncAttributeMaxDynamicSharedMemorySize, SMEMB);
    cudaFuncSetAttribute(attn_k,                  cudaFuncAttributeMaxDynamicSharedMemorySize, ATT_SMEM);

    const dim3 tb(256);
    // ---- weight conversion: QKV packed per layer, others transposed+split ----
    splitT_k<<<dim3(DD/32, DD/32, LL), tb>>>(wq, whi + OQKV,         wlo + OQKV,         DD, DD, 3*MEL);
    splitT_k<<<dim3(DD/32, DD/32, LL), tb>>>(wk, whi + OQKV + MEL,   wlo + OQKV + MEL,   DD, DD, 3*MEL);
    splitT_k<<<dim3(DD/32, DD/32, LL), tb>>>(wv, whi + OQKV + 2*MEL, wlo + OQKV + 2*MEL, DD, DD, 3*MEL);
    splitT_k<<<dim3(DD/32, DD/32, LL), tb>>>(wo, whi + OO,  wlo + OO,  DD, DD, MEL);
    splitT_k<<<dim3(D4/32, DD/32, LL), tb>>>(w1, whi + O1,  wlo + O1,  DD, D4, 4*MEL);
    splitT_k<<<dim3(DD/32, D4/32, LL), tb>>>(w2, whi + O2,  wlo + O2,  D4, DD, 4*MEL);
    split_k<<<(int)(MEL/4/256), tb>>>(wdelta, whi + ODl, wlo + ODl);

    const dim3 gQKV(3 * DD / BN, MT / BM);  // (24, 64)
    const dim3 gN(DD / BN, MT / BM);        // (8, 64)
    const dim3 gW(D4 / BN, MT / BM);        // (32, 64)
    const dim3 gA(BB * HH, SS / ABR);       // (64, 32)

    for (int li = 0; li < LL; li++) {
        const __nv_bfloat16* bQh = whi + OQKV + (size_t)li * 3 * MEL;
        const __nv_bfloat16* bQl = wlo + OQKV + (size_t)li * 3 * MEL;
        const __nv_bfloat16* boh = whi + OO  + (size_t)li * MEL;
        const __nv_bfloat16* bol = wlo + OO  + (size_t)li * MEL;
        const __nv_bfloat16* b1h = whi + O1  + (size_t)li * 4 * MEL;
        const __nv_bfloat16* b1l = wlo + O1  + (size_t)li * 4 * MEL;
        const __nv_bfloat16* b2h = whi + O2  + (size_t)li * 4 * MEL;
        const __nv_bfloat16* b2l = wlo + O2  + (size_t)li * 4 * MEL;

        const float* xin = (li == 0) ? latents : x;

        rmsns_k<<<MT, tb>>>(xin, ahi, alo);
        hgemm_k<EPI_QKV><<<gQKV, tb, SMEMB>>>(ahi, alo, bQh, bQl, nullptr, q, k, v,
                                              nullptr, nullptr, cosT, sinT, DD, DD);
        attn_k<<<gA, ATT_THR, ATT_SMEM>>>(q, k, v, ahi, alo);
        hgemm_k<EPI_RESID><<<gN, tb, SMEMB>>>(ahi, alo, boh, bol, xin, x, nullptr, nullptr,
                                              nullptr, nullptr, nullptr, nullptr, DD, DD);
        rmsns_k<<<MT, tb>>>(x, ahi, alo);
        hgemm_k<EPI_SILU_SPLIT><<<gW, tb, SMEMB>>>(ahi, alo, b1h, b1l, nullptr, nullptr, nullptr, nullptr,
                                                   ahi2, alo2, nullptr, nullptr, D4, DD);
        hgemm_k<EPI_RESID><<<gN, tb, SMEMB>>>(ahi2, alo2, b2h, b2l, x, x, nullptr, nullptr,
                                              nullptr, nullptr, nullptr, nullptr, DD, D4);
    }

    rmsns_k<<<MT, tb>>>(x, ahi, alo);
    hgemm_k<EPI_TANH><<<gN, tb, SMEMB>>>(ahi, alo, whi + ODl, wlo + ODl, nullptr, out, nullptr, nullptr,
                                         nullptr, nullptr, nullptr, nullptr, DD, DD);
}

// round 15
// speedup vs baseline: 1.2239x; 1.1297x over previous
#include <cuda_runtime.h>
#include <cuda_bf16.h>
#include <cstdint>
#include <cstddef>

// ---------------- Problem constants ----------------
#define BB 4
#define SS 2048
#define DD 1024
#define HH 16
#define HD 64
#define LL 4
#define WIN 256
#define MT (BB*SS)          // 8192 rows
#define D4 (4*DD)           // 4096

// ---------------- Scratch (device globals; no allocation) ----------------
__device__ float g_x [MT*DD];
__device__ __nv_bfloat16 g_qh[MT*DD];
__device__ __nv_bfloat16 g_ql[MT*DD];
__device__ __nv_bfloat16 g_kh[MT*DD];
__device__ __nv_bfloat16 g_kl[MT*DD];
__device__ __nv_bfloat16 g_vh[MT*DD];
__device__ __nv_bfloat16 g_vl[MT*DD];

#define MEL ((size_t)DD*DD)                 // 1M elems
#define AW2 ((size_t)MT*(DD+D4))
#define W_ELEMS  (49*MEL)
__device__ __nv_bfloat16 g_ahi[AW2];
__device__ __nv_bfloat16 g_alo[AW2];
__device__ __nv_bfloat16 g_whi[W_ELEMS];
__device__ __nv_bfloat16 g_wlo[W_ELEMS];

// weight region offsets (elements)
#define OQKV ((size_t)0)
#define OO  (12*MEL)
#define O1  (16*MEL)
#define O2  (32*MEL)
#define ODl (48*MEL)

// ---------------- small helpers ----------------
__device__ __forceinline__ uint32_t smem_u32(const void* p){
    uint32_t a;
    asm("{ .reg .u64 t; cvta.to.shared.u64 t, %1; cvt.u32.u64 %0, t; }"
        : "=r"(a) : "l"(p));
    return a;
}
__device__ __forceinline__ void cpa16(uint32_t s, const void* g){
    asm volatile("cp.async.cg.shared.global [%0], [%1], 16;" :: "r"(s), "l"(g));
}
__device__ __forceinline__ void ldsm4(uint32_t* d, uint32_t a){
    asm volatile("ldmatrix.sync.aligned.m8n8.x4.shared.b16 {%0,%1,%2,%3}, [%4];"
        : "=r"(d[0]), "=r"(d[1]), "=r"(d[2]), "=r"(d[3]) : "r"(a));
}
__device__ __forceinline__ void ldsm4t(uint32_t* d, uint32_t a){
    asm volatile("ldmatrix.sync.aligned.m8n8.x4.trans.shared.b16 {%0,%1,%2,%3}, [%4];"
        : "=r"(d[0]), "=r"(d[1]), "=r"(d[2]), "=r"(d[3]) : "r"(a));
}
__device__ __forceinline__ void mma16816(float* c, const uint32_t* a, const uint32_t* b){
    asm volatile("mma.sync.aligned.m16n8k16.row.col.f32.bf16.bf16.f32 "
        "{%0,%1,%2,%3}, {%4,%5,%6,%7}, {%8,%9}, {%0,%1,%2,%3};"
        : "+f"(c[0]), "+f"(c[1]), "+f"(c[2]), "+f"(c[3])
        : "r"(a[0]), "r"(a[1]), "r"(a[2]), "r"(a[3]), "r"(b[0]), "r"(b[1]));
}
__device__ __forceinline__ void st_split2(__nv_bfloat16* H, __nv_bfloat16* L,
                                          size_t off, float a, float b){
    __nv_bfloat16 ha = __float2bfloat16(a), hb = __float2bfloat16(b);
    *(__nv_bfloat162*)(H + off) = __halves2bfloat162(ha, hb);
    *(__nv_bfloat162*)(L + off) = __halves2bfloat162(
        __float2bfloat16(a - __bfloat162float(ha)),
        __float2bfloat16(b - __bfloat162float(hb)));
}
__device__ __forceinline__ uint32_t packbf(float a, float b){
    __nv_bfloat162 v = __halves2bfloat162(__float2bfloat16(a), __float2bfloat16(b));
    return *(uint32_t*)&v;
}

// ---------------- HMMA split-bf16 GEMM (R11 config: 128x128, 2 CTA/SM) ----------------
#define BM 128
#define BN 128
#define BK 32
#define ATILE (BM*64)
#define BTILE (BN*64)
#define STAGE (2*ATILE + 2*BTILE)
#define NSTG 3
#define SMEMB (NSTG*STAGE)            // 98304

__device__ __forceinline__ uint32_t swz(int r, int c){
    return (uint32_t)(r * 64 + ((c ^ ((r >> 1) & 3)) << 4));
}

enum { EPI_NONE = 0, EPI_SILU_SPLIT = 1, EPI_RESID = 2, EPI_TANH = 3, EPI_QKV = 5 };

template<int EPI>
__global__ __launch_bounds__(256, 2)
void hgemm_k(const __nv_bfloat16* __restrict__ Ahi, const __nv_bfloat16* __restrict__ Alo,
             const __nv_bfloat16* __restrict__ Bhi, const __nv_bfloat16* __restrict__ Blo,
             const float* __restrict__ R, float* __restrict__ C,
             __nv_bfloat16* __restrict__ Qh, __nv_bfloat16* __restrict__ Ql,
             __nv_bfloat16* __restrict__ Kh, __nv_bfloat16* __restrict__ Kl,
             __nv_bfloat16* __restrict__ Vh, __nv_bfloat16* __restrict__ Vl,
             __nv_bfloat16* __restrict__ Hh, __nv_bfloat16* __restrict__ Hl,
             const float* __restrict__ CO, const float* __restrict__ SI,
             int N, int K)
{
    extern __shared__ char sm[];
    const uint32_t sb = smem_u32(sm);
    const int tid  = threadIdx.x;
    const int warp = tid >> 5;
    const int lane = tid & 31;
    const int m0 = blockIdx.y * BM;
    const int n0 = blockIdx.x * BN;
    const int wm = warp >> 1;
    const int wn = warp & 1;

    auto issue = [&](int st, int kc) {
        uint32_t base = sb + st * STAGE;
        #pragma unroll
        for (int it = 0; it < 2; it++) {
            int i = tid + it * 256;
            int r = i >> 2, c = i & 3;
            uint32_t so = base + swz(r, c);
            size_t g = (size_t)(m0 + r) * K + kc + c * 8;
            cpa16(so,          Ahi + g);
            cpa16(so + ATILE,  Alo + g);
        }
        #pragma unroll
        for (int it = 0; it < 2; it++) {
            int i = tid + it * 256;
            int r = i >> 2, c = i & 3;
            uint32_t so = base + 2 * ATILE + swz(r, c);
            size_t g = (size_t)(n0 + r) * K + kc + c * 8;
            cpa16(so,          Bhi + g);
            cpa16(so + BTILE,  Blo + g);
        }
        asm volatile("cp.async.commit_group;");
    };

    float acc[2][8][4];
    #pragma unroll
    for (int i = 0; i < 2; i++)
        #pragma unroll
        for (int j = 0; j < 8; j++)
            #pragma unroll
            for (int e = 0; e < 4; e++) acc[i][j][e] = 0.f;

    const int nk = K / BK;
    issue(0, 0);
    issue(1, BK);
    int stg = 0;
    for (int i = 0; i < nk; i++) {
        if (i + 1 < nk) { asm volatile("cp.async.wait_group 1;"); }
        else            { asm volatile("cp.async.wait_group 0;"); }
        __syncthreads();
        if (i + 2 < nk) {
            int ns = stg + 2; if (ns >= NSTG) ns -= NSTG;
            issue(ns, (i + 2) * BK);
        }

        uint32_t base = sb + stg * STAGE;
        #pragma unroll
        for (int kk = 0; kk < 2; kk++) {
            uint32_t ah[2][4], al[2][4];
            #pragma unroll
            for (int mi = 0; mi < 2; mi++) {
                int r = wm * 32 + mi * 16 + (lane & 15);
                int c = kk * 2 + (lane >> 4);
                uint32_t ad = base + swz(r, c);
                ldsm4(ah[mi], ad);
                ldsm4(al[mi], ad + ATILE);
            }
            #pragma unroll
            for (int nh = 0; nh < 2; nh++) {
                uint32_t th[2][4], tl[2][4];
                #pragma unroll
                for (int p2 = 0; p2 < 2; p2++) {
                    int np = nh * 2 + p2;
                    int r = wn * 64 + np * 16 + (lane & 7) + ((lane >> 4) & 1) * 8;
                    int c = kk * 2 + ((lane >> 3) & 1);
                    uint32_t bd = base + 2 * ATILE + swz(r, c);
                    ldsm4(th[p2], bd);
                    ldsm4(tl[p2], bd + BTILE);
                }
                #pragma unroll
                for (int p2 = 0; p2 < 2; p2++) {
                    int np = nh * 2 + p2;
                    #pragma unroll
                    for (int mi = 0; mi < 2; mi++) {
                        mma16816(acc[mi][np*2],   ah[mi], th[p2]);
                        mma16816(acc[mi][np*2],   ah[mi], tl[p2]);
                        mma16816(acc[mi][np*2],   al[mi], th[p2]);
                        mma16816(acc[mi][np*2+1], ah[mi], th[p2] + 2);
                        mma16816(acc[mi][np*2+1], ah[mi], tl[p2] + 2);
                        mma16816(acc[mi][np*2+1], al[mi], th[p2] + 2);
                    }
                }
            }
        }
        if (++stg >= NSTG) stg = 0;
    }

    // ---- epilogue ----
    if (EPI == EPI_QKV) {
        int seg = n0 >> 10;
        int nb  = n0 & 1023;
        __nv_bfloat16* dh = (seg == 0) ? Qh : ((seg == 1) ? Kh : Vh);
        __nv_bfloat16* dl = (seg == 0) ? Ql : ((seg == 1) ? Kl : Vl);
        if (seg < 2) {
            #pragma unroll
            for (int mi = 0; mi < 2; mi++) {
                int row = m0 + wm * 32 + mi * 16 + (lane >> 2);
                int s0 = row & (SS - 1);
                int s1 = s0 + 8;
                #pragma unroll
                for (int np = 0; np < 4; np++) {
                    int d = np * 8 + (lane & 3) * 2;
                    float2 cA0 = *(const float2*)(CO + s0 * HD + d);
                    float2 sA0 = *(const float2*)(SI + s0 * HD + d);
                    float2 cB0 = *(const float2*)(CO + s0 * HD + d + 32);
                    float2 sB0 = *(const float2*)(SI + s0 * HD + d + 32);
                    float2 cA1 = *(const float2*)(CO + s1 * HD + d);
                    float2 sA1 = *(const float2*)(SI + s1 * HD + d);
                    float2 cB1 = *(const float2*)(CO + s1 * HD + d + 32);
                    float2 sB1 = *(const float2*)(SI + s1 * HD + d + 32);
                    float* x1 = acc[mi][np];
                    float* x2 = acc[mi][np + 4];
                    float o1[4], o2[4];
                    o1[0] = x1[0] * cA0.x - x2[0] * sA0.x;
                    o1[1] = x1[1] * cA0.y - x2[1] * sA0.y;
                    o1[2] = x1[2] * cA1.x - x2[2] * sA1.x;
                    o1[3] = x1[3] * cA1.y - x2[3] * sA1.y;
                    o2[0] = x2[0] * cB0.x + x1[0] * sB0.x;
                    o2[1] = x2[1] * cB0.y + x1[1] * sB0.y;
                    o2[2] = x2[2] * cB1.x + x1[2] * sB1.x;
                    o2[3] = x2[3] * cB1.y + x1[3] * sB1.y;
                    int col = nb + wn * 64 + d;
                    size_t g0 = (size_t)row * DD + col;
                    size_t g1 = (size_t)(row + 8) * DD + col;
                    st_split2(dh, dl, g0,      o1[0], o1[1]);
                    st_split2(dh, dl, g1,      o1[2], o1[3]);
                    st_split2(dh, dl, g0 + 32, o2[0], o2[1]);
                    st_split2(dh, dl, g1 + 32, o2[2], o2[3]);
                }
            }
        } else {
            #pragma unroll
            for (int mi = 0; mi < 2; mi++) {
                #pragma unroll
                for (int ni = 0; ni < 8; ni++) {
                    int row = m0 + wm * 32 + mi * 16 + (lane >> 2);
                    int col = nb + wn * 64 + ni * 8 + (lane & 3) * 2;
                    size_t g0 = (size_t)row * DD + col;
                    size_t g1 = (size_t)(row + 8) * DD + col;
                    st_split2(dh, dl, g0, acc[mi][ni][0], acc[mi][ni][1]);
                    st_split2(dh, dl, g1, acc[mi][ni][2], acc[mi][ni][3]);
                }
            }
        }
    } else {
        #pragma unroll
        for (int mi = 0; mi < 2; mi++) {
            #pragma unroll
            for (int ni = 0; ni < 8; ni++) {
                int row = m0 + wm * 32 + mi * 16 + (lane >> 2);
                int col = n0 + wn * 64 + ni * 8 + (lane & 3) * 2;
                float v[4] = { acc[mi][ni][0], acc[mi][ni][1], acc[mi][ni][2], acc[mi][ni][3] };
                size_t o0 = (size_t)row * N + col;
                size_t o1 = (size_t)(row + 8) * N + col;
                if (EPI == EPI_SILU_SPLIT) {
                    #pragma unroll
                    for (int e = 0; e < 4; e++) v[e] = v[e] / (1.0f + __expf(-v[e]));
                    st_split2(Hh, Hl, o0, v[0], v[1]);
                    st_split2(Hh, Hl, o1, v[2], v[3]);
                } else {
                    if (EPI == EPI_RESID) {
                        float2 r0 = *(const float2*)(R + o0);
                        float2 r1 = *(const float2*)(R + o1);
                        v[0] += r0.x; v[1] += r0.y; v[2] += r1.x; v[3] += r1.y;
                    } else if (EPI == EPI_TANH) {
                        #pragma unroll
                        for (int e = 0; e < 4; e++) v[e] = tanhf(v[e]);
                    }
                    *(float2*)(C + o0) = make_float2(v[0], v[1]);
                    *(float2*)(C + o1) = make_float2(v[2], v[3]);
                }
            }
        }
    }
}

// ---------------- fp32 -> bf16 hi/lo split (flat) ----------------
__global__ __launch_bounds__(256) void split_k(const float* __restrict__ x,
                                               __nv_bfloat16* __restrict__ hi,
                                               __nv_bfloat16* __restrict__ lo)
{
    size_t i = (size_t)blockIdx.x * 256 + threadIdx.x;
    float4 v = ((const float4*)x)[i];
    st_split2(hi, lo, i * 4,     v.x, v.y);
    st_split2(hi, lo, i * 4 + 2, v.z, v.w);
}

// ---------------- fp32 W[K,N] -> transposed bf16 hi/lo WT[N,K] ----------------
__global__ __launch_bounds__(256) void splitT_k(const float* __restrict__ src,
                                                __nv_bfloat16* __restrict__ hi,
                                                __nv_bfloat16* __restrict__ lo,
                                                int K, int N, size_t dstStride)
{
    __shared__ float t[32][33];
    src += (size_t)blockIdx.z * (size_t)K * N;
    hi  += (size_t)blockIdx.z * dstStride;
    lo  += (size_t)blockIdx.z * dstStride;
    int n0 = blockIdx.x * 32, k0 = blockIdx.y * 32;
    int tx = threadIdx.x & 31, ty = threadIdx.x >> 5;
    #pragma unroll
    for (int i = ty; i < 32; i += 8)
        t[i][tx] = src[(size_t)(k0 + i) * N + n0 + tx];
    __syncthreads();
    #pragma unroll
    for (int i = ty; i < 32; i += 8) {
        float v = t[tx][i];
        __nv_bfloat16 h = __float2bfloat16(v);
        size_t o = (size_t)(n0 + i) * K + k0 + tx;
        hi[o] = h;
        lo[o] = __float2bfloat16(v - __bfloat162float(h));
    }
}

// ---------------- RMSNorm fused with bf16 split ----------------
__global__ __launch_bounds__(256) void rmsns_k(const float* __restrict__ X,
                                               __nv_bfloat16* __restrict__ Hh,
                                               __nv_bfloat16* __restrict__ Hl)
{
    __shared__ float red[8];
    const int row = blockIdx.x;
    const int tid = threadIdx.x;
    const float4* x4 = (const float4*)(X + (size_t)row * DD);
    float4 v = x4[tid];
    float s = v.x * v.x + v.y * v.y + v.z * v.z + v.w * v.w;
    #pragma unroll
    for (int o = 16; o; o >>= 1) s += __shfl_xor_sync(0xffffffffu, s, o);
    if ((tid & 31) == 0) red[tid >> 5] = s;
    __syncthreads();
    float tot = red[0] + red[1] + red[2] + red[3] + red[4] + red[5] + red[6] + red[7];
    float inv = rsqrtf(tot * (1.0f / DD) + 1e-6f);
    size_t base = (size_t)row * DD + tid * 4;
    st_split2(Hh, Hl, base,     v.x * inv, v.y * inv);
    st_split2(Hh, Hl, base + 2, v.z * inv, v.w * inv);
}

// ---------------- HMMA sliding-window attention (split-bf16) ----------------
// q-tile 128, 8 warps (each owns a 16-row stripe), kv chunks of 64.
// Smem (bytes): Qh 0..16K, Ql 16K..32K, Kh 32K..40K, Kl 40K..48K, Vh 48K..56K, Vl 56K..64K
#define ABR 128
#define NCH 64
#define ATT_SMEM 65536
#define SQH 0
#define SQL 16384
#define SKH 32768
#define SKL 40960
#define SVH 49152
#define SVL 57344

__device__ __forceinline__ uint32_t swz128(int r, int c){
    return (uint32_t)(r * 128 + ((c ^ (r & 7)) << 4));
}

__global__ __launch_bounds__(256, 2)
void attn_k(const __nv_bfloat16* __restrict__ qh, const __nv_bfloat16* __restrict__ ql,
            const __nv_bfloat16* __restrict__ kh, const __nv_bfloat16* __restrict__ kl,
            const __nv_bfloat16* __restrict__ vh, const __nv_bfloat16* __restrict__ vl,
            __nv_bfloat16* __restrict__ Oh, __nv_bfloat16* __restrict__ Ol)
{
    extern __shared__ char sa[];
    const uint32_t sb = smem_u32(sa);
    const int tid  = threadIdx.x;
    const int warp = tid >> 5;
    const int lane = tid & 31;
    const int bh = blockIdx.x;
    const int b  = bh >> 4;
    const int h  = bh & 15;
    const int q0 = blockIdx.y * ABR;

    // load Q tile (128 x 64 bf16, hi+lo), swizzled for ldmatrix
    for (int i = tid; i < 1024; i += 256) {
        int r = i >> 3, c = i & 7;
        size_t gl = ((size_t)(b * SS + q0 + r) * HH + h) * HD + c * 8;
        uint32_t d = swz128(r, c);
        *(uint4*)(sa + SQH + d) = *(const uint4*)(qh + gl);
        *(uint4*)(sa + SQL + d) = *(const uint4*)(ql + gl);
    }

    float m0 = -1e30f, m1 = -1e30f, l0 = 0.f, l1 = 0.f;
    float onf[8][4];
    #pragma unroll
    for (int i = 0; i < 8; i++)
        #pragma unroll
        for (int e = 0; e < 4; e++) onf[i][e] = 0.f;

    const int row0 = q0 + warp * 16 + (lane >> 2);
    const int row1 = row0 + 8;

    int c0 = (q0 > WIN - 1) ? ((q0 - (WIN - 1)) & ~(NCH - 1)) : 0;
    for (int cb = c0; cb < q0 + ABR; cb += NCH) {
        __syncthreads();
        for (int i = tid; i < 512; i += 256) {
            int r = i >> 3, c = i & 7;
            size_t gl = ((size_t)(b * SS + cb + r) * HH + h) * HD + c * 8;
            uint32_t d = swz128(r, c);
            *(uint4*)(sa + SKH + d) = *(const uint4*)(kh + gl);
            *(uint4*)(sa + SKL + d) = *(const uint4*)(kl + gl);
            *(uint4*)(sa + SVH + d) = *(const uint4*)(vh + gl);
            *(uint4*)(sa + SVL + d) = *(const uint4*)(vl + gl);
        }
        __syncthreads();

        // ---- S = Q K^T (split 3-term) ----
        float sacc[8][4];
        #pragma unroll
        for (int i = 0; i < 8; i++)
            #pragma unroll
            for (int e = 0; e < 4; e++) sacc[i][e] = 0.f;

        #pragma unroll
        for (int ks = 0; ks < 4; ks++) {
            uint32_t aQh[4], aQl[4];
            {
                int r = warp * 16 + (lane & 15);
                int c = ks * 2 + (lane >> 4);
                uint32_t ad = sb + SQH + swz128(r, c);
                ldsm4(aQh, ad);
                ldsm4(aQl, ad + (SQL - SQH));
            }
            #pragma unroll
            for (int nh = 0; nh < 4; nh++) {
                uint32_t th[4], tl[4];
                int r = nh * 16 + (lane & 7) + ((lane >> 4) & 1) * 8;
                int c = ks * 2 + ((lane >> 3) & 1);
                uint32_t kd = sb + SKH + swz128(r, c);
                ldsm4(th, kd);
                ldsm4(tl, kd + (SKL - SKH));
                int nf = nh * 2;
                mma16816(sacc[nf],   aQh, th);
                mma16816(sacc[nf],   aQh, tl);
                mma16816(sacc[nf],   aQl, th);
                mma16816(sacc[nf+1], aQh, th + 2);
                mma16816(sacc[nf+1], aQh, tl + 2);
                mma16816(sacc[nf+1], aQl, th + 2);
            }
        }

        // ---- softmax update ----
        const int colb = cb + (lane & 3) * 2;
        float rm0 = -1e30f, rm1 = -1e30f;
        #pragma unroll
        for (int nf = 0; nf < 8; nf++) {
            int cc = colb + nf * 8;
            float s0 = sacc[nf][0] * 0.125f;
            float s1 = sacc[nf][1] * 0.125f;
            float s2 = sacc[nf][2] * 0.125f;
            float s3 = sacc[nf][3] * 0.125f;
            int d0 = row0 - cc, d1 = row0 - cc - 1;
            int d2 = row1 - cc, d3 = row1 - cc - 1;
            if (!(d0 >= 0 && d0 < WIN)) s0 = -1e9f;
            if (!(d1 >= 0 && d1 < WIN)) s1 = -1e9f;
            if (!(d2 >= 0 && d2 < WIN)) s2 = -1e9f;
            if (!(d3 >= 0 && d3 < WIN)) s3 = -1e9f;
            sacc[nf][0] = s0; sacc[nf][1] = s1; sacc[nf][2] = s2; sacc[nf][3] = s3;
            rm0 = fmaxf(rm0, fmaxf(s0, s1));
            rm1 = fmaxf(rm1, fmaxf(s2, s3));
        }
        rm0 = fmaxf(rm0, __shfl_xor_sync(0xffffffffu, rm0, 1));
        rm0 = fmaxf(rm0, __shfl_xor_sync(0xffffffffu, rm0, 2));
        rm1 = fmaxf(rm1, __shfl_xor_sync(0xffffffffu, rm1, 1));
        rm1 = fmaxf(rm1, __shfl_xor_sync(0xffffffffu, rm1, 2));
        float mn0 = fmaxf(m0, rm0), mn1 = fmaxf(m1, rm1);
        float sc0 = expf(m0 - mn0), sc1 = expf(m1 - mn1);
        m0 = mn0; m1 = mn1;

        float ls0 = 0.f, ls1 = 0.f;
        uint32_t phi[8][2], plo[8][2];
        #pragma unroll
        for (int nf = 0; nf < 8; nf++) {
            float p0 = __expf(sacc[nf][0] - mn0);
            float p1 = __expf(sacc[nf][1] - mn0);
            float p2 = __expf(sacc[nf][2] - mn1);
            float p3 = __expf(sacc[nf][3] - mn1);
            ls0 += p0 + p1;
            ls1 += p2 + p3;
            __nv_bfloat16 b0 = __float2bfloat16(p0), b1 = __float2bfloat16(p1);
            __nv_bfloat16 b2 = __float2bfloat16(p2), b3 = __float2bfloat16(p3);
            phi[nf][0] = packbf(p0, p1);
            phi[nf][1] = packbf(p2, p3);
            plo[nf][0] = packbf(p0 - __bfloat162float(b0), p1 - __bfloat162float(b1));
            plo[nf][1] = packbf(p2 - __bfloat162float(b2), p3 - __bfloat162float(b3));
        }
        ls0 += __shfl_xor_sync(0xffffffffu, ls0, 1);
        ls0 += __shfl_xor_sync(0xffffffffu, ls0, 2);
        ls1 += __shfl_xor_sync(0xffffffffu, ls1, 1);
        ls1 += __shfl_xor_sync(0xffffffffu, ls1, 2);
        l0 = l0 * sc0 + ls0;
        l1 = l1 * sc1 + ls1;
        #pragma unroll
        for (int nf = 0; nf < 8; nf++) {
            onf[nf][0] *= sc0; onf[nf][1] *= sc0;
            onf[nf][2] *= sc1; onf[nf][3] *= sc1;
        }

        // ---- O += P V (split 3-term); V fragments via ldmatrix.trans ----
        #pragma unroll
        for (int ks = 0; ks < 4; ks++) {
            uint32_t aPh[4] = { phi[2*ks][0], phi[2*ks][1], phi[2*ks+1][0], phi[2*ks+1][1] };
            uint32_t aPl[4] = { plo[2*ks][0], plo[2*ks][1], plo[2*ks+1][0], plo[2*ks+1][1] };
            #pragma unroll
            for (int dn = 0; dn < 4; dn++) {
                uint32_t bh4[4], bl4[4];
                int r = ks * 16 + (lane & 7) + ((lane >> 3) & 1) * 8;
                int c = dn * 2 + (lane >> 4);
                uint32_t vd = sb + SVH + swz128(r, c);
                ldsm4t(bh4, vd);
                ldsm4t(bl4, vd + (SVL - SVH));
                int nf = dn * 2;
                mma16816(onf[nf],   aPh, bh4);
                mma16816(onf[nf],   aPh, bl4);
                mma16816(onf[nf],   aPl, bh4);
                mma16816(onf[nf+1], aPh, bh4 + 2);
                mma16816(onf[nf+1], aPh, bl4 + 2);
                mma16816(onf[nf+1], aPl, bh4 + 2);
            }
        }
    }

    // ---- epilogue: normalize + split-bf16 store ----
    float il0 = 1.0f / l0, il1 = 1.0f / l1;
    size_t t0 = (size_t)(b * SS + q0 + warp * 16 + (lane >> 2)) * DD + h * 64 + (lane & 3) * 2;
    size_t t1 = t0 + (size_t)8 * DD;
    #pragma unroll
    for (int nf = 0; nf < 8; nf++) {
        st_split2(Oh, Ol, t0 + nf * 8, onf[nf][0] * il0, onf[nf][1] * il0);
        st_split2(Oh, Ol, t1 + nf * 8, onf[nf][2] * il1, onf[nf][3] * il1);
    }
}

// ---------------- host orchestration ----------------
extern "C" void kernel_launch(void* const* d_in, const int* in_sizes, int n_in,
                              void* d_out, int out_size)
{
    const float* latents = (const float*)d_in[0];
    const float* cosT    = (const float*)d_in[1];
    const float* sinT    = (const float*)d_in[2];
    const float* wq      = (const float*)d_in[3];
    const float* wk      = (const float*)d_in[4];
    const float* wv      = (const float*)d_in[5];
    const float* wo      = (const float*)d_in[6];
    const float* w1      = (const float*)d_in[7];
    const float* w2      = (const float*)d_in[8];
    const float* wdelta  = (const float*)d_in[9];
    float* out = (float*)d_out;

    float* x;
    __nv_bfloat16 *qh_, *ql_, *kh_, *kl_, *vh_, *vl_;
    __nv_bfloat16 *ahi, *alo, *whi, *wlo;
    cudaGetSymbolAddress((void**)&x,   g_x);
    cudaGetSymbolAddress((void**)&qh_, g_qh);
    cudaGetSymbolAddress((void**)&ql_, g_ql);
    cudaGetSymbolAddress((void**)&kh_, g_kh);
    cudaGetSymbolAddress((void**)&kl_, g_kl);
    cudaGetSymbolAddress((void**)&vh_, g_vh);
    cudaGetSymbolAddress((void**)&vl_, g_vl);
    cudaGetSymbolAddress((void**)&ahi, g_ahi);
    cudaGetSymbolAddress((void**)&alo, g_alo);
    cudaGetSymbolAddress((void**)&whi, g_whi);
    cudaGetSymbolAddress((void**)&wlo, g_wlo);

    __nv_bfloat16* ahi2 = ahi + (size_t)MT * DD;
    __nv_bfloat16* alo2 = alo + (size_t)MT * DD;

    cudaFuncSetAttribute(hgemm_k<EPI_QKV>,        cudaFuncAttributeMaxDynamicSharedMemorySize, SMEMB);
    cudaFuncSetAttribute(hgemm_k<EPI_SILU_SPLIT>, cudaFuncAttributeMaxDynamicSharedMemorySize, SMEMB);
    cudaFuncSetAttribute(hgemm_k<EPI_RESID>,      cudaFuncAttributeMaxDynamicSharedMemorySize, SMEMB);
    cudaFuncSetAttribute(hgemm_k<EPI_TANH>,       cudaFuncAttributeMaxDynamicSharedMemorySize, SMEMB);
    cudaFuncSetAttribute(attn_k,                  cudaFuncAttributeMaxDynamicSharedMemorySize, ATT_SMEM);

    const dim3 tb(256);
    // ---- weight conversion: QKV packed per layer, others transposed+split ----
    splitT_k<<<dim3(DD/32, DD/32, LL), tb>>>(wq, whi + OQKV,         wlo + OQKV,         DD, DD, 3*MEL);
    splitT_k<<<dim3(DD/32, DD/32, LL), tb>>>(wk, whi + OQKV + MEL,   wlo + OQKV + MEL,   DD, DD, 3*MEL);
    splitT_k<<<dim3(DD/32, DD/32, LL), tb>>>(wv, whi + OQKV + 2*MEL, wlo + OQKV + 2*MEL, DD, DD, 3*MEL);
    splitT_k<<<dim3(DD/32, DD/32, LL), tb>>>(wo, whi + OO,  wlo + OO,  DD, DD, MEL);
    splitT_k<<<dim3(D4/32, DD/32, LL), tb>>>(w1, whi + O1,  wlo + O1,  DD, D4, 4*MEL);
    splitT_k<<<dim3(DD/32, D4/32, LL), tb>>>(w2, whi + O2,  wlo + O2,  D4, DD, 4*MEL);
    split_k<<<(int)(MEL/4/256), tb>>>(wdelta, whi + ODl, wlo + ODl);

    const dim3 gQKV(3 * DD / BN, MT / BM);  // (24, 64)
    const dim3 gN(DD / BN, MT / BM);        // (8, 64)
    const dim3 gW(D4 / BN, MT / BM);        // (32, 64)
    const dim3 gA(BB * HH, SS / ABR);       // (64, 16)

    for (int li = 0; li < LL; li++) {
        const __nv_bfloat16* bQh = whi + OQKV + (size_t)li * 3 * MEL;
        const __nv_bfloat16* bQl = wlo + OQKV + (size_t)li * 3 * MEL;
        const __nv_bfloat16* boh = whi + OO  + (size_t)li * MEL;
        const __nv_bfloat16* bol = wlo + OO  + (size_t)li * MEL;
        const __nv_bfloat16* b1h = whi + O1  + (size_t)li * 4 * MEL;
        const __nv_bfloat16* b1l = wlo + O1  + (size_t)li * 4 * MEL;
        const __nv_bfloat16* b2h = whi + O2  + (size_t)li * 4 * MEL;
        const __nv_bfloat16* b2l = wlo + O2  + (size_t)li * 4 * MEL;

        const float* xin = (li == 0) ? latents : x;

        rmsns_k<<<MT, tb>>>(xin, ahi, alo);
        hgemm_k<EPI_QKV><<<gQKV, tb, SMEMB>>>(ahi, alo, bQh, bQl, nullptr, nullptr,
                                              qh_, ql_, kh_, kl_, vh_, vl_,
                                              nullptr, nullptr, cosT, sinT, DD, DD);
        attn_k<<<gA, tb, ATT_SMEM>>>(qh_, ql_, kh_, kl_, vh_, vl_, ahi, alo);
        hgemm_k<EPI_RESID><<<gN, tb, SMEMB>>>(ahi, alo, boh, bol, xin, x,
                                              nullptr, nullptr, nullptr, nullptr, nullptr, nullptr,
                                              nullptr, nullptr, nullptr, nullptr, DD, DD);
        rmsns_k<<<MT, tb>>>(x, ahi, alo);
        hgemm_k<EPI_SILU_SPLIT><<<gW, tb, SMEMB>>>(ahi, alo, b1h, b1l, nullptr, nullptr,
                                                   nullptr, nullptr, nullptr, nullptr, nullptr, nullptr,
                                                   ahi2, alo2, nullptr, nullptr, D4, DD);
        hgemm_k<EPI_RESID><<<gN, tb, SMEMB>>>(ahi2, alo2, b2h, b2l, x, x,
                                              nullptr, nullptr, nullptr, nullptr, nullptr, nullptr,
                                              nullptr, nullptr, nullptr, nullptr, DD, D4);
    }

    rmsns_k<<<MT, tb>>>(x, ahi, alo);
    hgemm_k<EPI_TANH><<<gN, tb, SMEMB>>>(ahi, alo, whi + ODl, wlo + ODl, nullptr, out,
                                         nullptr, nullptr, nullptr, nullptr, nullptr, nullptr,
                                         nullptr, nullptr, nullptr, nullptr, DD, DD);
}